// round 1
// baseline (speedup 1.0000x reference)
#include <cuda_runtime.h>

#define N_USERS 50000
#define N_ITEMS 50000
#define N_NODES 100000
#define NNZ     1600000
#define EMB     64
#define N_LAYERS 3
#define BATCH   4096
#define REG_L2  1e-5f

// Scratch (device globals: no allocation allowed)
__device__ float g_ego [(size_t)N_NODES * EMB];                 // 25.6 MB
__device__ float g_side[(size_t)N_NODES * EMB];                 // 25.6 MB
__device__ float g_all [(size_t)N_NODES * EMB * (N_LAYERS + 1)];// 102.4 MB
__device__ float g_acc[2];                                       // {sum logsig, sum l2}

__device__ __forceinline__ void red_add4(float* p, float a, float b, float c, float d) {
    asm volatile("red.global.add.v4.f32 [%0], {%1,%2,%3,%4};"
                 :: "l"(p), "f"(a), "f"(b), "f"(c), "f"(d) : "memory");
}

// ---------------------------------------------------------------------------
// Init: ego = concat(user_emb, item_emb); all_emb[:, 0:64] = ego; acc = 0
// ---------------------------------------------------------------------------
__global__ void init_kernel(const float* __restrict__ ue, const float* __restrict__ ie) {
    int t = blockIdx.x * 256 + threadIdx.x;          // N_NODES*16 threads
    if (t < 2) g_acc[t] = 0.f;
    int node = t >> 4, q = t & 15;
    const float* src = (node < N_USERS) ? (ue + (size_t)node * EMB)
                                        : (ie + (size_t)(node - N_USERS) * EMB);
    float4 v = *(const float4*)(src + q * 4);
    *(float4*)(g_ego + (size_t)node * EMB + q * 4)      = v;
    *(float4*)(g_all + (size_t)node * (EMB * 4) + q * 4) = v;
}

// ---------------------------------------------------------------------------
// SpMM: side[row] += val * ego[col]   (segment_sum via vector reductions)
// one thread per (nnz, quarter-row): NNZ*16 threads
// ---------------------------------------------------------------------------
__global__ void spmm_kernel(const float* __restrict__ val,
                            const int*   __restrict__ row,
                            const int*   __restrict__ col) {
    int t = blockIdx.x * 256 + threadIdx.x;
    int e = t >> 4, q = t & 15;
    int r = __ldg(row + e);
    int c = __ldg(col + e);
    float v = __ldg(val + e);
    float4 x = *(const float4*)(g_ego + (size_t)c * EMB + q * 4);
    red_add4(g_side + (size_t)r * EMB + q * 4, v * x.x, v * x.y, v * x.z, v * x.w);
}

// ---------------------------------------------------------------------------
// Transform: for each row:
//   x1 = side ; x2 = ego * (side - ego)
//   act = leaky_relu(x1 @ W_gc + x2 @ W_bi + (b_gc + b_bi))
//   ego = act ; all_emb[:, 64*(k+1):] = act / max(||act||, 1e-12)
// Block: 256 threads (8 warps), 8 rows per warp => 64 rows/block.
// Shared: W interleaved float4 (32KB) + bias (256B) + x staging (32KB)
// ---------------------------------------------------------------------------
#define TR_SMEM (2048 * 16 + 64 * 4 + 4096 * 8)

__global__ void __launch_bounds__(256) transform_kernel(
        const float* __restrict__ Wg, const float* __restrict__ bg,
        const float* __restrict__ Wb, const float* __restrict__ bb, int k) {
    extern __shared__ float sh[];
    float4* shW4 = (float4*)sh;                   // [j*32 + lane] -> {Wg[j][2l],Wg[j][2l+1],Wb[j][2l],Wb[j][2l+1]}
    float*  shB  = sh + 2048 * 4;                 // 64 floats: b_gc + b_bi
    float2* shX  = (float2*)(shB + 64);           // [warp][r][j] -> {x1[j], x2[j]}

    int tid = threadIdx.x;
    const float* Wg_k = Wg + k * 4096;
    const float* Wb_k = Wb + k * 4096;
    #pragma unroll
    for (int idx = tid; idx < 2048; idx += 256) {
        int j = idx >> 5, l = idx & 31;
        float2 g = *(const float2*)(Wg_k + j * 64 + l * 2);
        float2 b = *(const float2*)(Wb_k + j * 64 + l * 2);
        shW4[idx] = make_float4(g.x, g.y, b.x, b.y);
    }
    if (tid < 64) shB[tid] = bg[k * 64 + tid] + bb[k * 64 + tid];
    __syncthreads();

    int warp = tid >> 5, lane = tid & 31;
    int rowbase = (blockIdx.x * 8 + warp) * 8;
    float2* shXw = shX + warp * 512;              // 8 rows * 64 float2

    // Stage x1/x2 for 8 rows (lane covers j = 2*lane, 2*lane+1)
    #pragma unroll
    for (int r = 0; r < 8; r++) {
        int row = rowbase + r;
        float2 x1 = make_float2(0.f, 0.f), x2 = make_float2(0.f, 0.f);
        if (row < N_NODES) {
            float2 s = *(const float2*)(g_side + (size_t)row * EMB + lane * 2);
            float2 e = *(const float2*)(g_ego  + (size_t)row * EMB + lane * 2);
            x1 = s;
            x2 = make_float2(e.x * (s.x - e.x), e.y * (s.y - e.y));
        }
        ((float4*)(shXw + r * 64))[lane] = make_float4(x1.x, x2.x, x1.y, x2.y);
    }
    __syncwarp();

    float bx = shB[2 * lane], by = shB[2 * lane + 1];
    float2 acc[8];
    #pragma unroll
    for (int r = 0; r < 8; r++) acc[r] = make_float2(bx, by);

    #pragma unroll 4
    for (int j = 0; j < 64; j++) {
        float4 w = shW4[j * 32 + lane];
        #pragma unroll
        for (int r = 0; r < 8; r++) {
            float2 x = shXw[r * 64 + j];          // broadcast
            acc[r].x += x.x * w.x + x.y * w.z;
            acc[r].y += x.x * w.y + x.y * w.w;
        }
    }

    #pragma unroll
    for (int r = 0; r < 8; r++) {
        int row = rowbase + r;
        float v0 = acc[r].x, v1 = acc[r].y;
        v0 = (v0 >= 0.f) ? v0 : 0.01f * v0;
        v1 = (v1 >= 0.f) ? v1 : 0.01f * v1;
        float p = v0 * v0 + v1 * v1;
        #pragma unroll
        for (int o = 16; o; o >>= 1) p += __shfl_xor_sync(0xffffffffu, p, o);
        float scale = 1.f / fmaxf(sqrtf(p), 1e-12f);
        if (row < N_NODES) {
            *(float2*)(g_ego + (size_t)row * EMB + lane * 2) = make_float2(v0, v1);
            *(float2*)(g_all + (size_t)row * (EMB * 4) + (k + 1) * 64 + lane * 2)
                = make_float2(v0 * scale, v1 * scale);
        }
    }
}

// ---------------------------------------------------------------------------
// BPR loss accumulation: one warp per batch element
// ---------------------------------------------------------------------------
__global__ void loss_kernel(const int* __restrict__ u,
                            const int* __restrict__ ii,
                            const int* __restrict__ jj) {
    int warp = threadIdx.x >> 5, lane = threadIdx.x & 31;
    int b = blockIdx.x * 4 + warp;                 // grid 1024 x 128 threads
    const float* ur = g_all + (size_t)u[b] * 256;
    const float* pr = g_all + ((size_t)N_USERS + ii[b]) * 256;
    const float* nr = g_all + ((size_t)N_USERS + jj[b]) * 256;

    float dui = 0.f, duj = 0.f, l2 = 0.f;
    #pragma unroll
    for (int t = 0; t < 2; t++) {
        float4 uv = *(const float4*)(ur + lane * 8 + t * 4);
        float4 pv = *(const float4*)(pr + lane * 8 + t * 4);
        float4 nv = *(const float4*)(nr + lane * 8 + t * 4);
        dui += uv.x * pv.x + uv.y * pv.y + uv.z * pv.z + uv.w * pv.w;
        duj += uv.x * nv.x + uv.y * nv.y + uv.z * nv.z + uv.w * nv.w;
        l2  += uv.x * uv.x + uv.y * uv.y + uv.z * uv.z + uv.w * uv.w
             + pv.x * pv.x + pv.y * pv.y + pv.z * pv.z + pv.w * pv.w
             + nv.x * nv.x + nv.y * nv.y + nv.z * nv.z + nv.w * nv.w;
    }
    #pragma unroll
    for (int o = 16; o; o >>= 1) {
        dui += __shfl_xor_sync(0xffffffffu, dui, o);
        duj += __shfl_xor_sync(0xffffffffu, duj, o);
        l2  += __shfl_xor_sync(0xffffffffu, l2,  o);
    }
    if (lane == 0) {
        float diff = dui - duj;
        float lp = fminf(diff, 0.f) - log1pf(expf(-fabsf(diff)));  // log_sigmoid
        atomicAdd(&g_acc[0], lp);
        atomicAdd(&g_acc[1], 0.5f * l2);
    }
}

__global__ void finalize_kernel(float* out) {
    out[0] = -g_acc[0] / (float)BATCH + REG_L2 * (g_acc[1] / (float)BATCH);
}

// ---------------------------------------------------------------------------
extern "C" void kernel_launch(void* const* d_in, const int* in_sizes, int n_in,
                              void* d_out, int out_size) {
    const float* user_emb = (const float*)d_in[0];
    const float* item_emb = (const float*)d_in[1];
    const float* W_gc     = (const float*)d_in[2];
    const float* b_gc     = (const float*)d_in[3];
    const float* W_bi     = (const float*)d_in[4];
    const float* b_bi     = (const float*)d_in[5];
    const float* adj_val  = (const float*)d_in[6];
    const int*   adj_row  = (const int*)d_in[7];
    const int*   adj_col  = (const int*)d_in[8];
    const int*   u        = (const int*)d_in[9];
    const int*   i        = (const int*)d_in[10];
    const int*   j        = (const int*)d_in[11];
    float* out = (float*)d_out;

    void* side_ptr = nullptr;
    cudaGetSymbolAddress(&side_ptr, g_side);

    cudaFuncSetAttribute(transform_kernel,
                         cudaFuncAttributeMaxDynamicSharedMemorySize, TR_SMEM);

    init_kernel<<<(N_NODES * 16) / 256, 256>>>(user_emb, item_emb);

    for (int k = 0; k < N_LAYERS; k++) {
        cudaMemsetAsync(side_ptr, 0, (size_t)N_NODES * EMB * sizeof(float), 0);
        spmm_kernel<<<(NNZ * 16) / 256, 256>>>(adj_val, adj_row, adj_col);
        transform_kernel<<<(N_NODES + 63) / 64, 256, TR_SMEM>>>(W_gc, b_gc, W_bi, b_bi, k);
    }

    loss_kernel<<<BATCH / 4, 128>>>(u, i, j);
    finalize_kernel<<<1, 1>>>(out);
}

// round 2
// speedup vs baseline: 1.2593x; 1.2593x over previous
#include <cuda_runtime.h>

#define N_USERS 50000
#define N_ITEMS 50000
#define N_NODES 100000
#define NNZ     1600000
#define EMB     64
#define N_LAYERS 3
#define BATCH   4096
#define REG_L2  1e-5f

#define SCAN_CHUNK 512
#define NBLK ((N_NODES + SCAN_CHUNK - 1) / SCAN_CHUNK)   // 196

// Scratch (device globals: no allocation allowed)
__device__ float g_ego [(size_t)N_NODES * EMB];                  // 25.6 MB
__device__ float g_side[(size_t)N_NODES * EMB];                  // 25.6 MB
__device__ float g_all [(size_t)N_NODES * EMB * (N_LAYERS + 1)]; // 102.4 MB
__device__ float g_acc[2];                                        // {sum logsig, sum l2}

// CSR build scratch
__device__ int  g_cnt[N_NODES];
__device__ int  g_row_ptr[N_NODES + 1];
__device__ int  g_cur[N_NODES];
__device__ int  g_bsum[NBLK];
__device__ int2 g_csr[NNZ];                                      // {col, val bits}

// ---------------------------------------------------------------------------
// Init: ego = concat(user_emb, item_emb); all_emb[:, 0:64] = ego; acc = 0
// ---------------------------------------------------------------------------
__global__ void init_kernel(const float* __restrict__ ue, const float* __restrict__ ie) {
    int t = blockIdx.x * 256 + threadIdx.x;          // N_NODES*16 threads
    if (t < 2) g_acc[t] = 0.f;
    int node = t >> 4, q = t & 15;
    const float* src = (node < N_USERS) ? (ue + (size_t)node * EMB)
                                        : (ie + (size_t)(node - N_USERS) * EMB);
    float4 v = *(const float4*)(src + q * 4);
    *(float4*)(g_ego + (size_t)node * EMB + q * 4)       = v;
    *(float4*)(g_all + (size_t)node * (EMB * 4) + q * 4) = v;
}

// ---------------------------------------------------------------------------
// CSR build: histogram -> 2-level exclusive scan -> scatter
// ---------------------------------------------------------------------------
__global__ void hist_kernel(const int* __restrict__ row) {
    int t = blockIdx.x * 256 + threadIdx.x;
    if (t < NNZ) atomicAdd(&g_cnt[__ldg(row + t)], 1);
}

// per-block sums of g_cnt chunks
__global__ void scan1_kernel() {
    __shared__ int shw[16];
    int t = threadIdx.x;                              // 512 threads
    int i = blockIdx.x * SCAN_CHUNK + t;
    int v = (i < N_NODES) ? g_cnt[i] : 0;
    #pragma unroll
    for (int o = 16; o; o >>= 1) v += __shfl_xor_sync(0xffffffffu, v, o);
    if ((t & 31) == 0) shw[t >> 5] = v;
    __syncthreads();
    if (t < 32) {
        int s = (t < 16) ? shw[t] : 0;
        #pragma unroll
        for (int o = 8; o; o >>= 1) s += __shfl_xor_sync(0xffffffffu, s, o);
        if (t == 0) g_bsum[blockIdx.x] = s;
    }
}

// single-block exclusive scan of NBLK block sums (NBLK <= 256)
__global__ void scanB_kernel() {
    __shared__ int shw[8];
    int t = threadIdx.x;                              // 256 threads
    int lane = t & 31, w = t >> 5;
    int v = (t < NBLK) ? g_bsum[t] : 0;
    int inc = v;
    #pragma unroll
    for (int o = 1; o < 32; o <<= 1) {
        int n = __shfl_up_sync(0xffffffffu, inc, o);
        if (lane >= o) inc += n;
    }
    if (lane == 31) shw[w] = inc;
    __syncthreads();
    if (t < 32) {
        int s = (t < 8) ? shw[t] : 0;
        #pragma unroll
        for (int o = 1; o < 8; o <<= 1) {
            int n = __shfl_up_sync(0xffffffffu, s, o);
            if (lane >= o) s += n;
        }
        if (t < 8) shw[t] = s;                        // inclusive
    }
    __syncthreads();
    int base = (w > 0) ? shw[w - 1] : 0;
    if (t < NBLK) g_bsum[t] = base + inc - v;          // exclusive
}

// full exclusive scan: block scan + g_bsum base -> row_ptr, cur
__global__ void scan2_kernel() {
    __shared__ int shw[16];
    int t = threadIdx.x;                              // 512 threads
    int lane = t & 31, w = t >> 5;
    int i = blockIdx.x * SCAN_CHUNK + t;
    int v = (i < N_NODES) ? g_cnt[i] : 0;
    int inc = v;
    #pragma unroll
    for (int o = 1; o < 32; o <<= 1) {
        int n = __shfl_up_sync(0xffffffffu, inc, o);
        if (lane >= o) inc += n;
    }
    if (lane == 31) shw[w] = inc;
    __syncthreads();
    if (t < 32) {
        int s = (t < 16) ? shw[t] : 0;
        #pragma unroll
        for (int o = 1; o < 16; o <<= 1) {
            int n = __shfl_up_sync(0xffffffffu, s, o);
            if (lane >= o) s += n;
        }
        if (t < 16) shw[t] = s;
    }
    __syncthreads();
    int base = ((w > 0) ? shw[w - 1] : 0) + g_bsum[blockIdx.x];
    int ex = base + inc - v;
    if (i < N_NODES) { g_row_ptr[i] = ex; g_cur[i] = ex; }
    if (i == N_NODES) g_row_ptr[N_NODES] = NNZ;
}

__global__ void scatter_kernel(const int* __restrict__ row,
                               const int* __restrict__ col,
                               const float* __restrict__ val) {
    int t = blockIdx.x * 256 + threadIdx.x;
    if (t >= NNZ) return;
    int r = __ldg(row + t);
    int pos = atomicAdd(&g_cur[r], 1);
    g_csr[pos] = make_int2(__ldg(col + t), __float_as_int(__ldg(val + t)));
}

// ---------------------------------------------------------------------------
// SpMM (CSR gather): one warp per row; lane holds 2 output floats.
// ---------------------------------------------------------------------------
__global__ void __launch_bounds__(256) spmm_csr_kernel() {
    int gt = blockIdx.x * 256 + threadIdx.x;
    int row = gt >> 5, lane = gt & 31;
    if (row >= N_NODES) return;
    int beg = g_row_ptr[row], end = g_row_ptr[row + 1];
    float2 acc = make_float2(0.f, 0.f);
    #pragma unroll 2
    for (int e = beg; e < end; e++) {
        int2 cv = __ldg(&g_csr[e]);                   // broadcast (same addr all lanes)
        float v = __int_as_float(cv.y);
        float2 x = *(const float2*)(g_ego + (size_t)cv.x * EMB + lane * 2);
        acc.x += v * x.x;
        acc.y += v * x.y;
    }
    *(float2*)(g_side + (size_t)row * EMB + lane * 2) = acc;
}

// ---------------------------------------------------------------------------
// Transform (unchanged): leaky_relu(side@Wg + ego*(side-ego)@Wb + b) + norm
// ---------------------------------------------------------------------------
#define TR_SMEM (2048 * 16 + 64 * 4 + 4096 * 8)

__global__ void __launch_bounds__(256) transform_kernel(
        const float* __restrict__ Wg, const float* __restrict__ bg,
        const float* __restrict__ Wb, const float* __restrict__ bb, int k) {
    extern __shared__ float sh[];
    float4* shW4 = (float4*)sh;
    float*  shB  = sh + 2048 * 4;
    float2* shX  = (float2*)(shB + 64);

    int tid = threadIdx.x;
    const float* Wg_k = Wg + k * 4096;
    const float* Wb_k = Wb + k * 4096;
    #pragma unroll
    for (int idx = tid; idx < 2048; idx += 256) {
        int j = idx >> 5, l = idx & 31;
        float2 g = *(const float2*)(Wg_k + j * 64 + l * 2);
        float2 b = *(const float2*)(Wb_k + j * 64 + l * 2);
        shW4[idx] = make_float4(g.x, g.y, b.x, b.y);
    }
    if (tid < 64) shB[tid] = bg[k * 64 + tid] + bb[k * 64 + tid];
    __syncthreads();

    int warp = tid >> 5, lane = tid & 31;
    int rowbase = (blockIdx.x * 8 + warp) * 8;
    float2* shXw = shX + warp * 512;

    #pragma unroll
    for (int r = 0; r < 8; r++) {
        int row = rowbase + r;
        float2 x1 = make_float2(0.f, 0.f), x2 = make_float2(0.f, 0.f);
        if (row < N_NODES) {
            float2 s = *(const float2*)(g_side + (size_t)row * EMB + lane * 2);
            float2 e = *(const float2*)(g_ego  + (size_t)row * EMB + lane * 2);
            x1 = s;
            x2 = make_float2(e.x * (s.x - e.x), e.y * (s.y - e.y));
        }
        ((float4*)(shXw + r * 64))[lane] = make_float4(x1.x, x2.x, x1.y, x2.y);
    }
    __syncwarp();

    float bx = shB[2 * lane], by = shB[2 * lane + 1];
    float2 acc[8];
    #pragma unroll
    for (int r = 0; r < 8; r++) acc[r] = make_float2(bx, by);

    #pragma unroll 4
    for (int j = 0; j < 64; j++) {
        float4 w = shW4[j * 32 + lane];
        #pragma unroll
        for (int r = 0; r < 8; r++) {
            float2 x = shXw[r * 64 + j];
            acc[r].x += x.x * w.x + x.y * w.z;
            acc[r].y += x.x * w.y + x.y * w.w;
        }
    }

    #pragma unroll
    for (int r = 0; r < 8; r++) {
        int row = rowbase + r;
        float v0 = acc[r].x, v1 = acc[r].y;
        v0 = (v0 >= 0.f) ? v0 : 0.01f * v0;
        v1 = (v1 >= 0.f) ? v1 : 0.01f * v1;
        float p = v0 * v0 + v1 * v1;
        #pragma unroll
        for (int o = 16; o; o >>= 1) p += __shfl_xor_sync(0xffffffffu, p, o);
        float scale = 1.f / fmaxf(sqrtf(p), 1e-12f);
        if (row < N_NODES) {
            *(float2*)(g_ego + (size_t)row * EMB + lane * 2) = make_float2(v0, v1);
            *(float2*)(g_all + (size_t)row * (EMB * 4) + (k + 1) * 64 + lane * 2)
                = make_float2(v0 * scale, v1 * scale);
        }
    }
}

// ---------------------------------------------------------------------------
// BPR loss accumulation: one warp per batch element
// ---------------------------------------------------------------------------
__global__ void loss_kernel(const int* __restrict__ u,
                            const int* __restrict__ ii,
                            const int* __restrict__ jj) {
    int warp = threadIdx.x >> 5, lane = threadIdx.x & 31;
    int b = blockIdx.x * 4 + warp;
    const float* ur = g_all + (size_t)u[b] * 256;
    const float* pr = g_all + ((size_t)N_USERS + ii[b]) * 256;
    const float* nr = g_all + ((size_t)N_USERS + jj[b]) * 256;

    float dui = 0.f, duj = 0.f, l2 = 0.f;
    #pragma unroll
    for (int t = 0; t < 2; t++) {
        float4 uv = *(const float4*)(ur + lane * 8 + t * 4);
        float4 pv = *(const float4*)(pr + lane * 8 + t * 4);
        float4 nv = *(const float4*)(nr + lane * 8 + t * 4);
        dui += uv.x * pv.x + uv.y * pv.y + uv.z * pv.z + uv.w * pv.w;
        duj += uv.x * nv.x + uv.y * nv.y + uv.z * nv.z + uv.w * nv.w;
        l2  += uv.x * uv.x + uv.y * uv.y + uv.z * uv.z + uv.w * uv.w
             + pv.x * pv.x + pv.y * pv.y + pv.z * pv.z + pv.w * pv.w
             + nv.x * nv.x + nv.y * nv.y + nv.z * nv.z + nv.w * nv.w;
    }
    #pragma unroll
    for (int o = 16; o; o >>= 1) {
        dui += __shfl_xor_sync(0xffffffffu, dui, o);
        duj += __shfl_xor_sync(0xffffffffu, duj, o);
        l2  += __shfl_xor_sync(0xffffffffu, l2,  o);
    }
    if (lane == 0) {
        float diff = dui - duj;
        float lp = fminf(diff, 0.f) - log1pf(expf(-fabsf(diff)));
        atomicAdd(&g_acc[0], lp);
        atomicAdd(&g_acc[1], 0.5f * l2);
    }
}

__global__ void finalize_kernel(float* out) {
    out[0] = -g_acc[0] / (float)BATCH + REG_L2 * (g_acc[1] / (float)BATCH);
}

// ---------------------------------------------------------------------------
extern "C" void kernel_launch(void* const* d_in, const int* in_sizes, int n_in,
                              void* d_out, int out_size) {
    const float* user_emb = (const float*)d_in[0];
    const float* item_emb = (const float*)d_in[1];
    const float* W_gc     = (const float*)d_in[2];
    const float* b_gc     = (const float*)d_in[3];
    const float* W_bi     = (const float*)d_in[4];
    const float* b_bi     = (const float*)d_in[5];
    const float* adj_val  = (const float*)d_in[6];
    const int*   adj_row  = (const int*)d_in[7];
    const int*   adj_col  = (const int*)d_in[8];
    const int*   u        = (const int*)d_in[9];
    const int*   i        = (const int*)d_in[10];
    const int*   j        = (const int*)d_in[11];
    float* out = (float*)d_out;

    void* cnt_ptr = nullptr;
    cudaGetSymbolAddress(&cnt_ptr, g_cnt);

    cudaFuncSetAttribute(transform_kernel,
                         cudaFuncAttributeMaxDynamicSharedMemorySize, TR_SMEM);

    init_kernel<<<(N_NODES * 16) / 256, 256>>>(user_emb, item_emb);

    // ---- CSR build (once per launch; reused by all 3 layers) ----
    cudaMemsetAsync(cnt_ptr, 0, (size_t)N_NODES * sizeof(int), 0);
    hist_kernel<<<(NNZ + 255) / 256, 256>>>(adj_row);
    scan1_kernel<<<NBLK, SCAN_CHUNK>>>();
    scanB_kernel<<<1, 256>>>();
    scan2_kernel<<<NBLK, SCAN_CHUNK>>>();
    scatter_kernel<<<(NNZ + 255) / 256, 256>>>(adj_row, adj_col, adj_val);

    for (int k = 0; k < N_LAYERS; k++) {
        spmm_csr_kernel<<<(N_NODES * 32 + 255) / 256, 256>>>();
        transform_kernel<<<(N_NODES + 63) / 64, 256, TR_SMEM>>>(W_gc, b_gc, W_bi, b_bi, k);
    }

    loss_kernel<<<BATCH / 4, 128>>>(u, i, j);
    finalize_kernel<<<1, 1>>>(out);
}